// round 13
// baseline (speedup 1.0000x reference)
#include <cuda_runtime.h>
#include <cuda_fp16.h>
#include <cstdint>
#include <math.h>

#define B_ 32768
#define H_ 512

#define CTA_M 128
#define NTH 256
#define ROWB 144                     // 128B data (64 halves) + 16B pad
#define PLANE_B (128 * ROWB)         // 18432
#define STAGE_B (2 * PLANE_B)        // 36864: A, W
#define NSTAGE 3
#define SMEM_DYN (NSTAGE * STAGE_B)  // 110592 -> 2 CTAs/SM

#define PREP_ITEMS (B_ / 2)          // 16384 row-pair items
#define PPK_ITEMS  2304              // weight tiles: {768,768,256,512}
#define ALL_ITEMS  (PREP_ITEMS + PPK_ITEMS)

// ---- static device scratch ----
__device__ int g_cnt[2];
__device__ int g_bar;
__device__ int g_tile;
__device__ int g_done;
__device__ int g_rdy[2][256];
__device__ int g_idx[2][B_];
__device__ __align__(16) __half g_x1[2][(size_t)B_ * 1536];
__device__ __align__(16) __half g_le[(size_t)B_ * 512];
__device__ __align__(16) __half g_h1[2][(size_t)B_ * 512];
#define WI_TOTAL 4718592
__device__ __align__(16) __half g_w[WI_TOTAL];

__constant__ int c_jobK[4]  = {1536, 1536, 512, 1024};
__constant__ int c_wioff[4] = {0, 1572864, 3145728, 3670016};

// ---- PTX helpers (baseline ISA only) ----
__device__ __forceinline__ uint32_t smem_u32(const void* p) {
    uint32_t a;
    asm("{ .reg .u64 t; cvta.to.shared.u64 t, %1; cvt.u32.u64 %0, t; }" : "=r"(a) : "l"(p));
    return a;
}
#define CP_ASYNC16(d, s) asm volatile("cp.async.cg.shared.global [%0], [%1], 16;" :: "r"(d), "l"(s))
#define CP_COMMIT()      asm volatile("cp.async.commit_group;" ::: "memory")
#define CP_WAIT1()       asm volatile("cp.async.wait_group 1;" ::: "memory")
#define CP_WAIT0()       asm volatile("cp.async.wait_group 0;" ::: "memory")
#define LDSM_X4(r, addr) \
    asm volatile("ldmatrix.sync.aligned.m8n8.x4.shared.b16 {%0,%1,%2,%3}, [%4];" \
        : "=r"((r)[0]), "=r"((r)[1]), "=r"((r)[2]), "=r"((r)[3]) : "r"(addr))
#define MMA_F32ACC(c, a, b) \
    asm volatile("mma.sync.aligned.m16n8k16.row.col.f32.f16.f16.f32 " \
        "{%0,%1,%2,%3}, {%4,%5,%6,%7}, {%8,%9}, {%0,%1,%2,%3};" \
        : "+f"((c)[0]), "+f"((c)[1]), "+f"((c)[2]), "+f"((c)[3]) \
        : "r"((a)[0]), "r"((a)[1]), "r"((a)[2]), "r"((a)[3]), "r"((b)[0]), "r"((b)[1]))
#define LD_ACQ(v, p) asm volatile("ld.global.acquire.gpu.b32 %0, [%1];" : "=r"(v) : "l"(p))

// ---- stage loader ----
__device__ __forceinline__ void load_stage(uint32_t stu, int job, int br, int m0,
                                           int bx, int k0, int K, int wioff, int tid) {
    const __half* a;
    int astr, acol;
    if (job <= 1)      { a = g_x1[br]; astr = 1536; acol = k0; }
    else if (job == 2) { a = g_h1[0];  astr = 512;  acol = k0; }
    else {
        if (k0 < 512)  { a = g_h1[1];  astr = 512;  acol = k0; }
        else           { a = g_le;     astr = 512;  acol = k0 - 512; }
    }
#pragma unroll
    for (int i = 0; i < 4; ++i) {
        int idx = tid + i * NTH;
        int row = idx >> 3;
        int q   = idx & 7;
        uint32_t d = stu + row * ROWB + q * 16;
        CP_ASYNC16(d, a + (size_t)(m0 + row) * astr + acol + q * 8);
        int grow = bx * 128 + row;
        CP_ASYNC16(d + PLANE_B, g_w + wioff + (size_t)grow * K + k0 + q * 8);
    }
    CP_COMMIT();
}

// ---- persistent mega-kernel: prep -> device barrier -> work-stealing GEMM ----
__global__ void __launch_bounds__(NTH, 2)
mega_kernel(const float* __restrict__ nh, const float* __restrict__ nc,
            const float* __restrict__ lab, const float* __restrict__ le,
            const int* __restrict__ group,
            const float* w0h, const float* w0g, const float* w1h, const float* w1g,
            const float* w2h, const float* w2g, const float* w3h, const float* w3g,
            const float* __restrict__ bh0, const float* __restrict__ bg0,
            const float* __restrict__ bh1, const float* __restrict__ bg1,
            const float* __restrict__ bh2, const float* __restrict__ bg2,
            const float* __restrict__ bh3, const float* __restrict__ bg3,
            float* __restrict__ out, float* __restrict__ mask_out, int write_mask) {
    extern __shared__ char smem[];
    int bid = blockIdx.x;
    int tid = threadIdx.x;
    int nCTA = gridDim.x;
    __shared__ int s_p[2];
    __shared__ int s_tile;

    // ================= phase 1: prep (sharded) =================
    for (int it = bid; it < ALL_ITEMS; it += nCTA) {
        if (it < PREP_ITEMS) {
            int half = tid >> 7;
            int tid2 = tid & 127;
            int row  = it * 2 + half;
            int g = __ldg(group + row);
            if (tid2 == 0) {
                if (write_mask) mask_out[row] = (g == 2) ? 1.0f : 0.0f;
                if (g < 2) {
                    int p = atomicAdd(&g_cnt[g], 1);
                    g_idx[g][p] = row;
                    s_p[half] = p;
                }
            }
            __syncthreads();
            if (g == 2) {
                float4 z = make_float4(0.f, 0.f, 0.f, 0.f);
                reinterpret_cast<float4*>(out + (size_t)row * H_)[tid2] = z;
            } else {
                int p = s_p[half];
                __half* x = g_x1[g];
#pragma unroll
                for (int i = 0; i < 3; ++i) {
                    int c4 = tid2 + i * 128;
                    const float* srcp = (c4 < 128) ? nh : (c4 < 256) ? nc : lab;
                    int loc = (c4 & 127) * 4;
                    float4 v = *reinterpret_cast<const float4*>(srcp + (size_t)row * 512 + loc);
                    __half h[4];
                    h[0] = __float2half_rn(v.x); h[1] = __float2half_rn(v.y);
                    h[2] = __float2half_rn(v.z); h[3] = __float2half_rn(v.w);
                    *reinterpret_cast<uint2*>(x + (size_t)p * 1536 + c4 * 4) = *reinterpret_cast<uint2*>(h);
                }
                if (g == 1) {
                    float4 v = *reinterpret_cast<const float4*>(le + (size_t)row * 512 + tid2 * 4);
                    __half h[4];
                    h[0] = __float2half_rn(v.x); h[1] = __float2half_rn(v.y);
                    h[2] = __float2half_rn(v.z); h[3] = __float2half_rn(v.w);
                    *reinterpret_cast<uint2*>(g_le + (size_t)p * 512 + tid2 * 4) = *reinterpret_cast<uint2*>(h);
                }
            }
        } else {
            // weight prepack item, transpose tile in (reused) dynamic smem
            int b2 = it - PREP_ITEMS;
            int j, base_b;
            if (b2 < 768)       { j = 0; base_b = 0; }
            else if (b2 < 1536) { j = 1; base_b = 768; }
            else if (b2 < 1792) { j = 2; base_b = 1536; }
            else                { j = 3; base_b = 1792; }
            const float* Wh = (j == 0) ? w0h : (j == 1) ? w1h : (j == 2) ? w2h : w3h;
            const float* Wg = (j == 0) ? w0g : (j == 1) ? w1g : (j == 2) ? w2g : w3g;
            int K  = c_jobK[j];
            int nk = K / 32;
            int local = b2 - base_b;
            int k0 = (local % nk) * 32;
            int n0 = (local / nk) * 32;
            float* sh = (float*)smem;                 // 32*33*4 = 4224B
            float* sg = (float*)(smem + 4352);
            int tx = tid & 31, ty = tid >> 5;
#pragma unroll
            for (int i = 0; i < 4; ++i) {
                sh[(ty + 8 * i) * 33 + tx] = Wh[(size_t)(k0 + ty + 8 * i) * 512 + n0 + tx];
                sg[(ty + 8 * i) * 33 + tx] = Wg[(size_t)(k0 + ty + 8 * i) * 512 + n0 + tx];
            }
            __syncthreads();
            size_t base = (size_t)c_wioff[j];
#pragma unroll
            for (int i = 0; i < 4; ++i) {
                int n = n0 + ty + 8 * i;
                int k = k0 + tx;
                g_w[base + (size_t)(2 * n) * K + k]     = __float2half_rn(sh[tx * 33 + ty + 8 * i]);
                g_w[base + (size_t)(2 * n + 1) * K + k] = __float2half_rn(sg[tx * 33 + ty + 8 * i]);
            }
        }
        __syncthreads();    // protect s_p / smem tile reuse across iterations
    }

    // ================= device barrier (grid fully resident) =================
    if (tid == 0) {
        __threadfence();
        atomicAdd(&g_bar, 1);
        int v;
        while (true) {
            LD_ACQ(v, &g_bar);
            if (v >= nCTA) break;
            __nanosleep(64);
        }
    }
    __syncthreads();

    int mcnt0 = g_cnt[0], mcnt1 = g_cnt[1];
    int nby0 = (mcnt0 + CTA_M - 1) / CTA_M;
    int nby1 = (mcnt1 + CTA_M - 1) / CTA_M;
    int T0 = 8 * nby0, T1 = T0 + 8 * nby1, T2 = T1 + 8 * nby0, T3 = T2 + 8 * nby1;

    // ================= phase 2: work-stealing GEMM tiles =================
    uint32_t sb = smem_u32(smem);
    int wid = tid >> 5, lane = tid & 31;
    int wm = (wid & 3) * 32;
    int wn = (wid >> 2) * 64;
    int s0 = wid & 3;
    uint32_t a_off  = (uint32_t)(wm + (lane & 15)) * ROWB + ((lane >> 4) << 4);
    uint32_t b_rowl = (lane & 7);
    uint32_t b_pair = (lane >> 4);
    uint32_t b_kh   = ((lane >> 3) & 1) * 16;

    while (true) {
        __syncthreads();                 // s_tile + smem stages free for reuse
        if (tid == 0) s_tile = atomicAdd(&g_tile, 1);
        __syncthreads();
        int t = s_tile;
        if (t >= T3) break;

        int job, br, loc;
        if (t < T0)      { job = 0; br = 0; loc = t; }
        else if (t < T1) { job = 1; br = 1; loc = t - T0; }
        else if (t < T2) { job = 2; br = 0; loc = t - T1; }
        else             { job = 3; br = 1; loc = t - T2; }
        int by = loc >> 3, bx = loc & 7;
        int mcnt = br ? mcnt1 : mcnt0;
        int m0 = by * CTA_M;

        if (job >= 2) {                  // wait for this row-slice of h1
            if (tid == 0) {
                const int* ctr = &g_rdy[br][by];
                int v;
                while (true) {
                    LD_ACQ(v, ctr);
                    if (v >= 8) break;
                    __nanosleep(128);
                }
            }
            __syncthreads();
        }

        int K = c_jobK[job];
        int wioff = c_wioff[job];

        float acc[2][8][4];
#pragma unroll
        for (int i = 0; i < 2; ++i)
#pragma unroll
            for (int j2 = 0; j2 < 8; ++j2)
#pragma unroll
                for (int q = 0; q < 4; ++q) acc[i][j2][q] = 0.f;

        const int nchunks = K / 64;
        load_stage(sb, job, br, m0, bx, 0, K, wioff, tid);

        int slot = 0;
        for (int c = 0; c < nchunks; ++c) {
            int nslot = (slot + 1 == NSTAGE) ? 0 : slot + 1;
            if (c + 1 < nchunks) {
                load_stage(sb + nslot * STAGE_B, job, br, m0, bx, (c + 1) * 64, K, wioff, tid);
                CP_WAIT1();
            } else {
                CP_WAIT0();
            }
            __syncthreads();
            uint32_t stu = sb + slot * STAGE_B;
            slot = nslot;

#pragma unroll
            for (int si = 0; si < 4; ++si) {
                int s = (si + s0) & 3;
                uint32_t koff = (uint32_t)s * 32;
                uint32_t ah[2][4];
#pragma unroll
                for (int tm = 0; tm < 2; ++tm)
                    LDSM_X4(ah[tm], stu + a_off + tm * 16 * ROWB + koff);
                uint32_t bf[8][2];
#pragma unroll
                for (int tn = 0; tn < 8; tn += 2) {
                    uint32_t row = wn + (tn + b_pair) * 8 + b_rowl;
                    uint32_t addr = stu + PLANE_B + row * ROWB + koff + b_kh;
                    uint32_t r[4];
                    LDSM_X4(r, addr);
                    bf[tn][0] = r[0]; bf[tn][1] = r[1];
                    bf[tn + 1][0] = r[2]; bf[tn + 1][1] = r[3];
                }
#pragma unroll
                for (int tm = 0; tm < 2; ++tm)
#pragma unroll
                    for (int tn = 0; tn < 8; ++tn) MMA_F32ACC(acc[tm][tn], ah[tm], bf[tn]);
            }
        }

        // ---- epilogue ----
        const float* bh_p = (job == 0) ? bh0 : (job == 1) ? bh1 : (job == 2) ? bh2 : bh3;
        const float* bg_p = (job == 0) ? bg0 : (job == 1) ? bg1 : (job == 2) ? bg2 : bg3;
        int n_base = bx * 64 + (wid >> 2) * 32 + (lane & 3);
        int m_base = m0 + wm + (lane >> 2);
        __half* h1 = g_h1[br];

#pragma unroll
        for (int tn = 0; tn < 8; ++tn) {
            int n = n_base + tn * 4;
            float bhv = __ldg(bh_p + n);
            float bgv = __ldg(bg_p + n);
#pragma unroll
            for (int tm = 0; tm < 2; ++tm)
#pragma unroll
                for (int rr = 0; rr < 2; ++rr) {
                    int m = m_base + tm * 16 + rr * 8;
                    if (m < mcnt) {
                        float x = acc[tm][tn][rr * 2 + 0] + bhv;
                        float y = acc[tm][tn][rr * 2 + 1] + bgv;
                        float r = tanhf(x) * (1.0f / (1.0f + __expf(-y)));
                        if (job < 2) {
                            h1[(size_t)m * 512 + n] = __float2half_rn(r);
                        } else {
                            out[(size_t)g_idx[br][m] * 512 + n] = r;
                        }
                    }
                }
        }

        if (job < 2) {                   // publish slice completion (release)
            __threadfence();
            __syncthreads();
            if (tid == 0) atomicAdd(&g_rdy[br][by], 1);
        }
    }

    // ================= reset ticket for next graph replay =================
    if (tid == 0) {
        int tkt = atomicAdd(&g_done, 1);
        if (tkt == nCTA - 1) {
            g_cnt[0] = 0; g_cnt[1] = 0;
            g_bar = 0; g_tile = 0; g_done = 0;
            for (int i = 0; i < 256; ++i) { g_rdy[0][i] = 0; g_rdy[1][i] = 0; }
            __threadfence();
        }
    }
}

// ---- launch ----
extern "C" void kernel_launch(void* const* d_in, const int* in_sizes, int n_in,
                              void* d_out, int out_size) {
    const float* node_hidden     = (const float*)d_in[0];
    const float* node_context    = (const float*)d_in[1];
    const float* label_embedding = (const float*)d_in[2];
    const float* left_embedding  = (const float*)d_in[3];
    const int*   group           = (const int*)  d_in[4];
    const float* Wl1h = (const float*)d_in[5];
    const float* bl1h = (const float*)d_in[6];
    const float* Wl1g = (const float*)d_in[7];
    const float* bl1g = (const float*)d_in[8];
    const float* Wl2h = (const float*)d_in[9];
    const float* bl2h = (const float*)d_in[10];
    const float* Wl2g = (const float*)d_in[11];
    const float* bl2g = (const float*)d_in[12];
    const float* Wr1h = (const float*)d_in[13];
    const float* br1h = (const float*)d_in[14];
    const float* Wr1g = (const float*)d_in[15];
    const float* br1g = (const float*)d_in[16];
    const float* Wr2h = (const float*)d_in[17];
    const float* br2h = (const float*)d_in[18];
    const float* Wr2g = (const float*)d_in[19];
    const float* br2g = (const float*)d_in[20];
    (void)in_sizes; (void)n_in;

    float* out_children = (float*)d_out;
    float* out_mask     = (float*)d_out + (size_t)B_ * H_;
    int write_mask = (out_size >= (int)((size_t)B_ * H_ + B_)) ? 1 : 0;

    static int nSM = 0;
    if (nSM == 0) {
        if (cudaDeviceGetAttribute(&nSM, cudaDevAttrMultiProcessorCount, 0) != cudaSuccess
            || nSM <= 0)
            nSM = 148;                   // conservative fallback
    }
    int grid = 2 * nSM;                  // exactly 2 CTAs/SM, fully resident

    cudaFuncSetAttribute(mega_kernel, cudaFuncAttributeMaxDynamicSharedMemorySize, SMEM_DYN);

    mega_kernel<<<grid, NTH, SMEM_DYN>>>(
        node_hidden, node_context, label_embedding, left_embedding, group,
        Wl1h, Wl1g, Wr1h, Wr1g, Wl2h, Wl2g, Wr2h, Wr2g,
        bl1h, bl1g, br1h, br1g, bl2h, bl2g, br2h, br2g,
        out_children, out_mask, write_mask);
}

// round 14
// speedup vs baseline: 1.1230x; 1.1230x over previous
#include <cuda_runtime.h>
#include <cuda_fp16.h>
#include <cstdint>
#include <math.h>

#define B_ 32768
#define H_ 512

#define CTA_M 256
#define NTH 512
#define ROWB 144                     // 128B data (64 halves) + 16B pad
#define A_PLANE (256 * ROWB)         // 36864
#define W_PLANE (128 * ROWB)         // 18432
#define STAGE_B (A_PLANE + W_PLANE)  // 55296
#define NSTAGE 3
#define SMEM_DYN (NSTAGE * STAGE_B)  // 165888 -> 1 CTA/SM

// ---- static device scratch ----
__device__ int g_cnt[2];
__device__ int g_done;
__device__ int g_rdy[2][128];        // per-(branch, 256-row slice) completion
__device__ int g_idx[2][B_];
__device__ __align__(16) __half g_x1[2][(size_t)B_ * 1536];
__device__ __align__(16) __half g_le[(size_t)B_ * 512];
__device__ __align__(16) __half g_h1[2][(size_t)B_ * 512];
#define WI_TOTAL 4718592
__device__ __align__(16) __half g_w[WI_TOTAL];

__constant__ int c_jobK[4]  = {1536, 1536, 512, 1024};
__constant__ int c_wioff[4] = {0, 1572864, 3145728, 3670016};

#define PREP_BLOCKS   (B_ / 2)
#define PPK_BASE      PREP_BLOCKS
#define PPK_TOTAL     2304
#define ALL_BLOCKS    (PREP_BLOCKS + PPK_TOTAL)
#define PREP_NTH      256

// ---- PTX helpers (baseline ISA only) ----
__device__ __forceinline__ uint32_t smem_u32(const void* p) {
    uint32_t a;
    asm("{ .reg .u64 t; cvta.to.shared.u64 t, %1; cvt.u32.u64 %0, t; }" : "=r"(a) : "l"(p));
    return a;
}
#define CP_ASYNC16(d, s) asm volatile("cp.async.cg.shared.global [%0], [%1], 16;" :: "r"(d), "l"(s))
#define CP_COMMIT()      asm volatile("cp.async.commit_group;" ::: "memory")
#define CP_WAIT1()       asm volatile("cp.async.wait_group 1;" ::: "memory")
#define CP_WAIT0()       asm volatile("cp.async.wait_group 0;" ::: "memory")
#define LDSM_X4(r, addr) \
    asm volatile("ldmatrix.sync.aligned.m8n8.x4.shared.b16 {%0,%1,%2,%3}, [%4];" \
        : "=r"((r)[0]), "=r"((r)[1]), "=r"((r)[2]), "=r"((r)[3]) : "r"(addr))
#define MMA_F32ACC(c, a, b) \
    asm volatile("mma.sync.aligned.m16n8k16.row.col.f32.f16.f16.f32 " \
        "{%0,%1,%2,%3}, {%4,%5,%6,%7}, {%8,%9}, {%0,%1,%2,%3};" \
        : "+f"((c)[0]), "+f"((c)[1]), "+f"((c)[2]), "+f"((c)[3]) \
        : "r"((a)[0]), "r"((a)[1]), "r"((a)[2]), "r"((a)[3]), "r"((b)[0]), "r"((b)[1]))
#define LD_ACQ(v, p) asm volatile("ld.global.acquire.gpu.b32 %0, [%1];" : "=r"(v) : "l"(p))

// ---- fused prep + weight prepack (separate launch; R12-proven, 47us @68% DRAM) ----
__global__ void __launch_bounds__(PREP_NTH)
prep_all_kernel(const float* __restrict__ nh, const float* __restrict__ nc,
                const float* __restrict__ lab, const float* __restrict__ le,
                const int* __restrict__ group,
                float* __restrict__ out_children,
                float* __restrict__ mask_out, int write_mask,
                const float* w0h, const float* w0g, const float* w1h, const float* w1g,
                const float* w2h, const float* w2g, const float* w3h, const float* w3g) {
    int bid = blockIdx.x;
    int tid = threadIdx.x;

    if (bid < PREP_BLOCKS) {
        int half = tid >> 7;
        int tid2 = tid & 127;
        int row  = bid * 2 + half;
        int g = __ldg(group + row);
        __shared__ int s_p[2];
        if (tid2 == 0) {
            if (write_mask) mask_out[row] = (g == 2) ? 1.0f : 0.0f;
            if (g < 2) {
                int p = atomicAdd(&g_cnt[g], 1);
                g_idx[g][p] = row;
                s_p[half] = p;
            }
        }
        __syncthreads();
        if (g == 2) {
            float4 z = make_float4(0.f, 0.f, 0.f, 0.f);
            reinterpret_cast<float4*>(out_children + (size_t)row * H_)[tid2] = z;
            return;
        }
        int p = s_p[half];
        __half* x = g_x1[g];
#pragma unroll
        for (int i = 0; i < 3; ++i) {
            int c4 = tid2 + i * 128;
            const float* srcp = (c4 < 128) ? nh : (c4 < 256) ? nc : lab;
            int loc = (c4 & 127) * 4;
            float4 v = *reinterpret_cast<const float4*>(srcp + (size_t)row * 512 + loc);
            __half h[4];
            h[0] = __float2half_rn(v.x); h[1] = __float2half_rn(v.y);
            h[2] = __float2half_rn(v.z); h[3] = __float2half_rn(v.w);
            *reinterpret_cast<uint2*>(x + (size_t)p * 1536 + c4 * 4) = *reinterpret_cast<uint2*>(h);
        }
        if (g == 1) {
            float4 v = *reinterpret_cast<const float4*>(le + (size_t)row * 512 + tid2 * 4);
            __half h[4];
            h[0] = __float2half_rn(v.x); h[1] = __float2half_rn(v.y);
            h[2] = __float2half_rn(v.z); h[3] = __float2half_rn(v.w);
            *reinterpret_cast<uint2*>(g_le + (size_t)p * 512 + tid2 * 4) = *reinterpret_cast<uint2*>(h);
        }
        return;
    }

    // weight prepack role
    int b2 = bid - PPK_BASE;
    int j, base_b;
    if (b2 < 768)       { j = 0; base_b = 0; }
    else if (b2 < 1536) { j = 1; base_b = 768; }
    else if (b2 < 1792) { j = 2; base_b = 1536; }
    else                { j = 3; base_b = 1792; }
    const float* Wh = (j == 0) ? w0h : (j == 1) ? w1h : (j == 2) ? w2h : w3h;
    const float* Wg = (j == 0) ? w0g : (j == 1) ? w1g : (j == 2) ? w2g : w3g;
    int K  = c_jobK[j];
    int nk = K / 32;
    int local = b2 - base_b;
    int k0 = (local % nk) * 32;
    int n0 = (local / nk) * 32;

    __shared__ float sh[32][33], sg[32][33];
    int tx = tid & 31, ty = tid >> 5;
#pragma unroll
    for (int i = 0; i < 4; ++i) {
        sh[ty + 8 * i][tx] = Wh[(size_t)(k0 + ty + 8 * i) * 512 + n0 + tx];
        sg[ty + 8 * i][tx] = Wg[(size_t)(k0 + ty + 8 * i) * 512 + n0 + tx];
    }
    __syncthreads();
    size_t base = (size_t)c_wioff[j];
#pragma unroll
    for (int i = 0; i < 4; ++i) {
        int n = n0 + ty + 8 * i;
        int k = k0 + tx;
        g_w[base + (size_t)(2 * n) * K + k]     = __float2half_rn(sh[tx][ty + 8 * i]);
        g_w[base + (size_t)(2 * n + 1) * K + k] = __float2half_rn(sg[tx][ty + 8 * i]);
    }
}

// ---- stage loader: A (256 rows) + W (128 rows), 128B each, 512 threads ----
__device__ __forceinline__ void load_stage(uint32_t stu, int job, int br, int m0,
                                           int bx, int k0, int K, int wioff, int tid) {
    const __half* a;
    int astr, acol;
    if (job <= 1)      { a = g_x1[br]; astr = 1536; acol = k0; }
    else if (job == 2) { a = g_h1[0];  astr = 512;  acol = k0; }
    else {
        if (k0 < 512)  { a = g_h1[1];  astr = 512;  acol = k0; }
        else           { a = g_le;     astr = 512;  acol = k0 - 512; }
    }
#pragma unroll
    for (int i = 0; i < 4; ++i) {              // A: 256 rows x 8 chunks = 2048
        int idx = tid + i * NTH;
        int row = idx >> 3;
        int q   = idx & 7;
        CP_ASYNC16(stu + row * ROWB + q * 16,
                   a + (size_t)(m0 + row) * astr + acol + q * 8);
    }
#pragma unroll
    for (int i = 0; i < 2; ++i) {              // W: 128 rows x 8 chunks = 1024
        int idx = tid + i * NTH;
        int row = idx >> 3;
        int q   = idx & 7;
        CP_ASYNC16(stu + A_PLANE + row * ROWB + q * 16,
                   g_w + wioff + (size_t)(bx * 128 + row) * K + k0 + q * 8);
    }
    CP_COMMIT();
}

// ---- ALL four gated GEMMs, CTA tile 256x64(logical), 512 thr, 1 CTA/SM ----
__global__ void __launch_bounds__(NTH, 1)
gate_gemm_all(const float* __restrict__ bh0, const float* __restrict__ bg0,
              const float* __restrict__ bh1, const float* __restrict__ bg1,
              const float* __restrict__ bh2, const float* __restrict__ bg2,
              const float* __restrict__ bh3, const float* __restrict__ bg3,
              float* __restrict__ out) {
    extern __shared__ char smem[];
    int job = (int)blockIdx.z;
    int br  = (job == 1 || job == 3) ? 1 : 0;
    int mcnt = g_cnt[br];
    int m0 = blockIdx.y * CTA_M;
    int tid = threadIdx.x;
    bool active = (m0 < mcnt);

    if (active) {
        if (job >= 2) {                        // wait for this 256-row h1 slice
            if (tid == 0) {
                const int* ctr = &g_rdy[br][blockIdx.y];
                int v;
                while (true) {
                    LD_ACQ(v, ctr);
                    if (v >= 8) break;
                    __nanosleep(128);
                }
            }
            __syncthreads();
        }

        int bx = blockIdx.x;
        int K  = c_jobK[job];
        int wioff = c_wioff[job];
        uint32_t sb = smem_u32(smem);

        float acc[2][8][4];
#pragma unroll
        for (int i = 0; i < 2; ++i)
#pragma unroll
            for (int j2 = 0; j2 < 8; ++j2)
#pragma unroll
                for (int q = 0; q < 4; ++q) acc[i][j2][q] = 0.f;

        const int nchunks = K / 64;
        load_stage(sb, job, br, m0, bx, 0, K, wioff, tid);

        int wid = tid >> 5, lane = tid & 31;   // 16 warps
        int wm = (wid & 7) * 32;               // 8 M-groups x 32 rows
        int wn = (wid >> 3) * 64;              // 2 N-groups x 64 W-rows
        int s0 = wid & 3;                      // stagger
        uint32_t a_off  = (uint32_t)(wm + (lane & 15)) * ROWB + ((lane >> 4) << 4);
        uint32_t b_rowl = (lane & 7);
        uint32_t b_pair = (lane >> 4);
        uint32_t b_kh   = ((lane >> 3) & 1) * 16;

        int slot = 0;
        for (int c = 0; c < nchunks; ++c) {
            int nslot = (slot + 1 == NSTAGE) ? 0 : slot + 1;
            if (c + 1 < nchunks) {
                load_stage(sb + nslot * STAGE_B, job, br, m0, bx, (c + 1) * 64, K, wioff, tid);
                CP_WAIT1();
            } else {
                CP_WAIT0();
            }
            __syncthreads();
            uint32_t stu = sb + slot * STAGE_B;
            slot = nslot;

#pragma unroll
            for (int si = 0; si < 4; ++si) {
                int s = (si + s0) & 3;
                uint32_t koff = (uint32_t)s * 32;
                uint32_t ah[2][4];
#pragma unroll
                for (int tm = 0; tm < 2; ++tm)
                    LDSM_X4(ah[tm], stu + a_off + tm * 16 * ROWB + koff);
                uint32_t bf[8][2];
#pragma unroll
                for (int tn = 0; tn < 8; tn += 2) {
                    uint32_t row = wn + (tn + b_pair) * 8 + b_rowl;
                    uint32_t addr = stu + A_PLANE + row * ROWB + koff + b_kh;
                    uint32_t r[4];
                    LDSM_X4(r, addr);
                    bf[tn][0] = r[0]; bf[tn][1] = r[1];
                    bf[tn + 1][0] = r[2]; bf[tn + 1][1] = r[3];
                }
#pragma unroll
                for (int tm = 0; tm < 2; ++tm)
#pragma unroll
                    for (int tn = 0; tn < 8; ++tn) MMA_F32ACC(acc[tm][tn], ah[tm], bf[tn]);
            }
        }

        // ---- epilogue ----
        const float* bh_p = (job == 0) ? bh0 : (job == 1) ? bh1 : (job == 2) ? bh2 : bh3;
        const float* bg_p = (job == 0) ? bg0 : (job == 1) ? bg1 : (job == 2) ? bg2 : bg3;
        int n_base = bx * 64 + (wid >> 3) * 32 + (lane & 3);
        int m_base = m0 + wm + (lane >> 2);
        __half* h1 = g_h1[br];

#pragma unroll
        for (int tn = 0; tn < 8; ++tn) {
            int n = n_base + tn * 4;
            float bhv = __ldg(bh_p + n);
            float bgv = __ldg(bg_p + n);
#pragma unroll
            for (int tm = 0; tm < 2; ++tm)
#pragma unroll
                for (int rr = 0; rr < 2; ++rr) {
                    int m = m_base + tm * 16 + rr * 8;
                    if (m < mcnt) {
                        float x = acc[tm][tn][rr * 2 + 0] + bhv;
                        float y = acc[tm][tn][rr * 2 + 1] + bgv;
                        float r = tanhf(x) * (1.0f / (1.0f + __expf(-y)));
                        if (job < 2) {
                            h1[(size_t)m * 512 + n] = __float2half_rn(r);
                        } else {
                            out[(size_t)g_idx[br][m] * 512 + n] = r;
                        }
                    }
                }
        }

        if (job < 2) {                         // publish slice completion (release)
            __threadfence();
            __syncthreads();
            if (tid == 0) atomicAdd(&g_rdy[br][blockIdx.y], 1);
        }
    }

    // ---- chip-wide completion ticket: last CTA resets state for next replay ----
    __syncthreads();
    if (tid == 0) {
        int total = gridDim.x * gridDim.y * gridDim.z;
        int t = atomicAdd(&g_done, 1);
        if (t == total - 1) {
            g_cnt[0] = 0;
            g_cnt[1] = 0;
            for (int i = 0; i < 128; ++i) { g_rdy[0][i] = 0; g_rdy[1][i] = 0; }
            g_done = 0;
            __threadfence();
        }
    }
}

// ---- launch ----
extern "C" void kernel_launch(void* const* d_in, const int* in_sizes, int n_in,
                              void* d_out, int out_size) {
    const float* node_hidden     = (const float*)d_in[0];
    const float* node_context    = (const float*)d_in[1];
    const float* label_embedding = (const float*)d_in[2];
    const float* left_embedding  = (const float*)d_in[3];
    const int*   group           = (const int*)  d_in[4];
    const float* Wl1h = (const float*)d_in[5];
    const float* bl1h = (const float*)d_in[6];
    const float* Wl1g = (const float*)d_in[7];
    const float* bl1g = (const float*)d_in[8];
    const float* Wl2h = (const float*)d_in[9];
    const float* bl2h = (const float*)d_in[10];
    const float* Wl2g = (const float*)d_in[11];
    const float* bl2g = (const float*)d_in[12];
    const float* Wr1h = (const float*)d_in[13];
    const float* br1h = (const float*)d_in[14];
    const float* Wr1g = (const float*)d_in[15];
    const float* br1g = (const float*)d_in[16];
    const float* Wr2h = (const float*)d_in[17];
    const float* br2h = (const float*)d_in[18];
    const float* Wr2g = (const float*)d_in[19];
    const float* br2g = (const float*)d_in[20];
    (void)in_sizes; (void)n_in;

    float* out_children = (float*)d_out;
    float* out_mask     = (float*)d_out + (size_t)B_ * H_;
    int write_mask = (out_size >= (int)((size_t)B_ * H_ + B_)) ? 1 : 0;

    cudaFuncSetAttribute(gate_gemm_all, cudaFuncAttributeMaxDynamicSharedMemorySize, SMEM_DYN);

    prep_all_kernel<<<ALL_BLOCKS, PREP_NTH>>>(node_hidden, node_context, label_embedding,
                                              left_embedding, group, out_children,
                                              out_mask, write_mask,
                                              Wl1h, Wl1g, Wr1h, Wr1g,
                                              Wl2h, Wl2g, Wr2h, Wr2g);

    // all 4 GEMM jobs, CTA tile 256 rows: z = job; layer-2 overlaps layer-1 tail
    dim3 grid(H_ / 64, B_ / CTA_M, 4);         // 8 x 128 x 4; idle CTAs exit fast
    gate_gemm_all<<<grid, NTH, SMEM_DYN>>>(bl1h, bl1g, br1h, br1g,
                                           bl2h, bl2g, br2h, br2g, out_children);
}

// round 15
// speedup vs baseline: 1.1475x; 1.0219x over previous
#include <cuda_runtime.h>
#include <cuda_fp16.h>
#include <cstdint>
#include <math.h>

#define B_ 32768
#define H_ 512

#define CTA_M 128
#define NTH 256
#define ROWB 144                     // 128B data (64 halves) + 16B pad
#define PLANE_B (128 * ROWB)         // 18432
#define STAGE_B (2 * PLANE_B)        // 36864: A, W
#define NSTAGE 3
#define SMEM_DYN (NSTAGE * STAGE_B)  // 110592 -> 2 CTAs/SM

// ---- static device scratch ----
__device__ int g_cnt[2];
__device__ int g_done;
__device__ int g_rdy[2][256];        // per-(branch, by) slice-completion counters
__device__ int g_idx[2][B_];
__device__ __align__(16) __half g_x1[2][(size_t)B_ * 1536];
__device__ __align__(16) __half g_le[(size_t)B_ * 512];
__device__ __align__(16) __half g_h1[2][(size_t)B_ * 512];
#define WI_TOTAL 4718592
__device__ __align__(16) __half g_w[WI_TOTAL];

__constant__ int c_jobK[4]  = {1536, 1536, 512, 1024};
__constant__ int c_wioff[4] = {0, 1572864, 3145728, 3670016};

#define PREP_BLOCKS   (B_ / 2)       // 16384, two rows per block
#define PPK_BASE      PREP_BLOCKS
#define PPK_TOTAL     2304
#define ALL_BLOCKS    (PREP_BLOCKS + PPK_TOTAL)

// ---- PTX helpers (baseline ISA only; no arch-'a' features) ----
__device__ __forceinline__ uint32_t smem_u32(const void* p) {
    uint32_t a;
    asm("{ .reg .u64 t; cvta.to.shared.u64 t, %1; cvt.u32.u64 %0, t; }" : "=r"(a) : "l"(p));
    return a;
}
#define CP_ASYNC16(d, s) asm volatile("cp.async.cg.shared.global [%0], [%1], 16;" :: "r"(d), "l"(s))
#define CP_COMMIT()      asm volatile("cp.async.commit_group;" ::: "memory")
#define CP_WAIT1()       asm volatile("cp.async.wait_group 1;" ::: "memory")
#define CP_WAIT0()       asm volatile("cp.async.wait_group 0;" ::: "memory")
#define LDSM_X4(r, addr) \
    asm volatile("ldmatrix.sync.aligned.m8n8.x4.shared.b16 {%0,%1,%2,%3}, [%4];" \
        : "=r"((r)[0]), "=r"((r)[1]), "=r"((r)[2]), "=r"((r)[3]) : "r"(addr))
#define MMA_F32ACC(c, a, b) \
    asm volatile("mma.sync.aligned.m16n8k16.row.col.f32.f16.f16.f32 " \
        "{%0,%1,%2,%3}, {%4,%5,%6,%7}, {%8,%9}, {%0,%1,%2,%3};" \
        : "+f"((c)[0]), "+f"((c)[1]), "+f"((c)[2]), "+f"((c)[3]) \
        : "r"((a)[0]), "r"((a)[1]), "r"((a)[2]), "r"((a)[3]), "r"((b)[0]), "r"((b)[1]))
#define LD_ACQ(v, p) asm volatile("ld.global.acquire.gpu.b32 %0, [%1];" : "=r"(v) : "l"(p))

// ---- fused prep + weight prepack (one launch) ----
__global__ void __launch_bounds__(NTH)
prep_all_kernel(const float* __restrict__ nh, const float* __restrict__ nc,
                const float* __restrict__ lab, const float* __restrict__ le,
                const int* __restrict__ group,
                float* __restrict__ out_children,
                float* __restrict__ mask_out, int write_mask,
                const float* w0h, const float* w0g, const float* w1h, const float* w1g,
                const float* w2h, const float* w2g, const float* w3h, const float* w3g) {
    int bid = blockIdx.x;
    int tid = threadIdx.x;

    if (bid < PREP_BLOCKS) {
        int half = tid >> 7;
        int tid2 = tid & 127;
        int row  = bid * 2 + half;
        int g = __ldg(group + row);
        __shared__ int s_p[2];
        if (tid2 == 0) {
            if (write_mask) mask_out[row] = (g == 2) ? 1.0f : 0.0f;
            if (g < 2) {
                int p = atomicAdd(&g_cnt[g], 1);
                g_idx[g][p] = row;
                s_p[half] = p;
            }
        }
        __syncthreads();
        if (g == 2) {
            float4 z = make_float4(0.f, 0.f, 0.f, 0.f);
            reinterpret_cast<float4*>(out_children + (size_t)row * H_)[tid2] = z;
            return;
        }
        int p = s_p[half];
        __half* x = g_x1[g];
        // batch the three segment loads first (MLP), then convert+store
        float4 v0 = *reinterpret_cast<const float4*>(nh  + (size_t)row * 512 + tid2 * 4);
        float4 v1 = *reinterpret_cast<const float4*>(nc  + (size_t)row * 512 + tid2 * 4);
        float4 v2 = *reinterpret_cast<const float4*>(lab + (size_t)row * 512 + tid2 * 4);
        float4 vl;
        if (g == 1) vl = *reinterpret_cast<const float4*>(le + (size_t)row * 512 + tid2 * 4);
        float4 vs[3] = { v0, v1, v2 };
#pragma unroll
        for (int i = 0; i < 3; ++i) {
            __half h[4];
            h[0] = __float2half_rn(vs[i].x); h[1] = __float2half_rn(vs[i].y);
            h[2] = __float2half_rn(vs[i].z); h[3] = __float2half_rn(vs[i].w);
            *reinterpret_cast<uint2*>(x + (size_t)p * 1536 + (i * 128 + tid2) * 4) =
                *reinterpret_cast<uint2*>(h);
        }
        if (g == 1) {
            __half h[4];
            h[0] = __float2half_rn(vl.x); h[1] = __float2half_rn(vl.y);
            h[2] = __float2half_rn(vl.z); h[3] = __float2half_rn(vl.w);
            *reinterpret_cast<uint2*>(g_le + (size_t)p * 512 + tid2 * 4) =
                *reinterpret_cast<uint2*>(h);
        }
        return;
    }

    // ---- weight prepack role ----
    int b2 = bid - PPK_BASE;
    int j, base_b;
    if (b2 < 768)       { j = 0; base_b = 0; }
    else if (b2 < 1536) { j = 1; base_b = 768; }
    else if (b2 < 1792) { j = 2; base_b = 1536; }
    else                { j = 3; base_b = 1792; }
    const float* Wh = (j == 0) ? w0h : (j == 1) ? w1h : (j == 2) ? w2h : w3h;
    const float* Wg = (j == 0) ? w0g : (j == 1) ? w1g : (j == 2) ? w2g : w3g;
    int K  = c_jobK[j];
    int nk = K / 32;
    int local = b2 - base_b;
    int k0 = (local % nk) * 32;
    int n0 = (local / nk) * 32;

    __shared__ float sh[32][33], sg[32][33];
    int tx = tid & 31, ty = tid >> 5;
#pragma unroll
    for (int i = 0; i < 4; ++i) {
        sh[ty + 8 * i][tx] = Wh[(size_t)(k0 + ty + 8 * i) * 512 + n0 + tx];
        sg[ty + 8 * i][tx] = Wg[(size_t)(k0 + ty + 8 * i) * 512 + n0 + tx];
    }
    __syncthreads();
    size_t base = (size_t)c_wioff[j];
#pragma unroll
    for (int i = 0; i < 4; ++i) {
        int n = n0 + ty + 8 * i;
        int k = k0 + tx;
        g_w[base + (size_t)(2 * n) * K + k]     = __float2half_rn(sh[tx][ty + 8 * i]);
        g_w[base + (size_t)(2 * n + 1) * K + k] = __float2half_rn(sg[tx][ty + 8 * i]);
    }
}

// ---- stage loader ----
__device__ __forceinline__ void load_stage(uint32_t stu, int job, int br, int m0,
                                           int bx, int k0, int K, int wioff, int tid) {
    const __half* a;
    int astr, acol;
    if (job <= 1)      { a = g_x1[br]; astr = 1536; acol = k0; }
    else if (job == 2) { a = g_h1[0];  astr = 512;  acol = k0; }
    else {
        if (k0 < 512)  { a = g_h1[1];  astr = 512;  acol = k0; }
        else           { a = g_le;     astr = 512;  acol = k0 - 512; }
    }
#pragma unroll
    for (int i = 0; i < 4; ++i) {
        int idx = tid + i * NTH;
        int row = idx >> 3;
        int q   = idx & 7;
        uint32_t d = stu + row * ROWB + q * 16;
        CP_ASYNC16(d, a + (size_t)(m0 + row) * astr + acol + q * 8);
        int grow = bx * 128 + row;
        CP_ASYNC16(d + PLANE_B, g_w + wioff + (size_t)grow * K + k0 + q * 8);
    }
    CP_COMMIT();
}

// ---- ALL four gated GEMMs in ONE launch (R12 structure) ----
__global__ void __launch_bounds__(NTH, 2)
gate_gemm_all(const float* __restrict__ bh0, const float* __restrict__ bg0,
              const float* __restrict__ bh1, const float* __restrict__ bg1,
              const float* __restrict__ bh2, const float* __restrict__ bg2,
              const float* __restrict__ bh3, const float* __restrict__ bg3,
              float* __restrict__ out) {
    extern __shared__ char smem[];
    int job = (int)blockIdx.z;
    int br  = (job == 1 || job == 3) ? 1 : 0;
    int mcnt = g_cnt[br];
    int m0 = blockIdx.y * CTA_M;
    int tid = threadIdx.x;
    bool active = (m0 < mcnt);

    if (active) {
        if (job >= 2) {
            if (tid == 0) {
                const int* ctr = &g_rdy[br][blockIdx.y];
                int v;
                while (true) {
                    LD_ACQ(v, ctr);
                    if (v >= 8) break;
                    __nanosleep(128);
                }
            }
            __syncthreads();
        }

        int bx = blockIdx.x;
        int K  = c_jobK[job];
        int wioff = c_wioff[job];
        uint32_t sb = smem_u32(smem);

        float acc[2][8][4];
#pragma unroll
        for (int i = 0; i < 2; ++i)
#pragma unroll
            for (int j2 = 0; j2 < 8; ++j2)
#pragma unroll
                for (int q = 0; q < 4; ++q) acc[i][j2][q] = 0.f;

        const int nchunks = K / 64;
        load_stage(sb, job, br, m0, bx, 0, K, wioff, tid);

        int wid = tid >> 5, lane = tid & 31;
        int wm = (wid & 3) * 32;
        int wn = (wid >> 2) * 64;
        uint32_t a_off  = (uint32_t)(wm + (lane & 15)) * ROWB + ((lane >> 4) << 4);
        uint32_t b_rowl = (lane & 7);
        uint32_t b_pair = (lane >> 4);
        uint32_t b_kh   = ((lane >> 3) & 1) * 16;

        int slot = 0;
        for (int c = 0; c < nchunks; ++c) {
            int nslot = (slot + 1 == NSTAGE) ? 0 : slot + 1;
            if (c + 1 < nchunks) {
                load_stage(sb + nslot * STAGE_B, job, br, m0, bx, (c + 1) * 64, K, wioff, tid);
                CP_WAIT1();
            } else {
                CP_WAIT0();
            }
            __syncthreads();
            uint32_t stu = sb + slot * STAGE_B;
            slot = nslot;

            int s0 = (wid + c) & 3;      // chunk-rotating stagger: phases never re-lock
#pragma unroll
            for (int si = 0; si < 4; ++si) {
                int s = (si + s0) & 3;
                uint32_t koff = (uint32_t)s * 32;
                uint32_t ah[2][4];
#pragma unroll
                for (int tm = 0; tm < 2; ++tm)
                    LDSM_X4(ah[tm], stu + a_off + tm * 16 * ROWB + koff);
                uint32_t bf[8][2];
#pragma unroll
                for (int tn = 0; tn < 8; tn += 2) {
                    uint32_t row = wn + (tn + b_pair) * 8 + b_rowl;
                    uint32_t addr = stu + PLANE_B + row * ROWB + koff + b_kh;
                    uint32_t r[4];
                    LDSM_X4(r, addr);
                    bf[tn][0] = r[0]; bf[tn][1] = r[1];
                    bf[tn + 1][0] = r[2]; bf[tn + 1][1] = r[3];
                }
#pragma unroll
                for (int tm = 0; tm < 2; ++tm)
#pragma unroll
                    for (int tn = 0; tn < 8; ++tn) MMA_F32ACC(acc[tm][tn], ah[tm], bf[tn]);
            }
        }

        // ---- epilogue ----
        const float* bh_p = (job == 0) ? bh0 : (job == 1) ? bh1 : (job == 2) ? bh2 : bh3;
        const float* bg_p = (job == 0) ? bg0 : (job == 1) ? bg1 : (job == 2) ? bg2 : bg3;
        int n_base = bx * 64 + (wid >> 2) * 32 + (lane & 3);
        int m_base = m0 + wm + (lane >> 2);
        __half* h1 = g_h1[br];

#pragma unroll
        for (int tn = 0; tn < 8; ++tn) {
            int n = n_base + tn * 4;
            float bhv = __ldg(bh_p + n);
            float bgv = __ldg(bg_p + n);
#pragma unroll
            for (int tm = 0; tm < 2; ++tm)
#pragma unroll
                for (int rr = 0; rr < 2; ++rr) {
                    int m = m_base + tm * 16 + rr * 8;
                    if (m < mcnt) {
                        float x = acc[tm][tn][rr * 2 + 0] + bhv;
                        float y = acc[tm][tn][rr * 2 + 1] + bgv;
                        float r = tanhf(x) * (1.0f / (1.0f + __expf(-y)));
                        if (job < 2) {
                            h1[(size_t)m * 512 + n] = __float2half_rn(r);
                        } else {
                            out[(size_t)g_idx[br][m] * 512 + n] = r;
                        }
                    }
                }
        }

        if (job < 2) {                   // publish slice completion (release)
            __threadfence();
            __syncthreads();
            if (tid == 0) atomicAdd(&g_rdy[br][blockIdx.y], 1);
        }
    }

    // ---- chip-wide completion ticket: last CTA resets state for next replay ----
    __syncthreads();
    if (tid == 0) {
        int total = gridDim.x * gridDim.y * gridDim.z;
        int t = atomicAdd(&g_done, 1);
        if (t == total - 1) {
            g_cnt[0] = 0;
            g_cnt[1] = 0;
            for (int i = 0; i < 256; ++i) { g_rdy[0][i] = 0; g_rdy[1][i] = 0; }
            g_done = 0;
            __threadfence();
        }
    }
}

// ---- launch ----
extern "C" void kernel_launch(void* const* d_in, const int* in_sizes, int n_in,
                              void* d_out, int out_size) {
    const float* node_hidden     = (const float*)d_in[0];
    const float* node_context    = (const float*)d_in[1];
    const float* label_embedding = (const float*)d_in[2];
    const float* left_embedding  = (const float*)d_in[3];
    const int*   group           = (const int*)  d_in[4];
    const float* Wl1h = (const float*)d_in[5];
    const float* bl1h = (const float*)d_in[6];
    const float* Wl1g = (const float*)d_in[7];
    const float* bl1g = (const float*)d_in[8];
    const float* Wl2h = (const float*)d_in[9];
    const float* bl2h = (const float*)d_in[10];
    const float* Wl2g = (const float*)d_in[11];
    const float* bl2g = (const float*)d_in[12];
    const float* Wr1h = (const float*)d_in[13];
    const float* br1h = (const float*)d_in[14];
    const float* Wr1g = (const float*)d_in[15];
    const float* br1g = (const float*)d_in[16];
    const float* Wr2h = (const float*)d_in[17];
    const float* br2h = (const float*)d_in[18];
    const float* Wr2g = (const float*)d_in[19];
    const float* br2g = (const float*)d_in[20];
    (void)in_sizes; (void)n_in;

    float* out_children = (float*)d_out;
    float* out_mask     = (float*)d_out + (size_t)B_ * H_;
    int write_mask = (out_size >= (int)((size_t)B_ * H_ + B_)) ? 1 : 0;

    cudaFuncSetAttribute(gate_gemm_all, cudaFuncAttributeMaxDynamicSharedMemorySize, SMEM_DYN);

    prep_all_kernel<<<ALL_BLOCKS, NTH>>>(node_hidden, node_context, label_embedding,
                                         left_embedding, group, out_children,
                                         out_mask, write_mask,
                                         Wl1h, Wl1g, Wr1h, Wr1g,
                                         Wl2h, Wl2g, Wr2h, Wr2g);

    dim3 grid(H_ / 64, B_ / CTA_M, 4);
    gate_gemm_all<<<grid, NTH, SMEM_DYN>>>(bl1h, bl1g, br1h, br1g,
                                           bl2h, bl2g, br2h, br2g, out_children);
}

// round 17
// speedup vs baseline: 1.1907x; 1.0376x over previous
#include <cuda_runtime.h>
#include <cuda_fp16.h>
#include <cstdint>
#include <math.h>

#define B_ 32768
#define H_ 512

#define CTA_M 128
#define NTH 256
#define ROWB 144                     // 128B data (64 halves) + 16B pad
#define PLANE_B (128 * ROWB)         // 18432
#define STAGE_B (2 * PLANE_B)        // 36864: A, W
#define NSTAGE 3
#define SMEM_DYN (NSTAGE * STAGE_B)  // 110592 -> 2 CTAs/SM

#define GRID_Y 96                    // y-stride covers up to 256 slices

// ---- static device scratch ----
__device__ int g_cnt[2];
__device__ int g_done;
__device__ int g_rdy[2][256];        // per-(branch, by) slice-completion counters
__device__ int g_idx[2][B_];
__device__ __align__(16) __half g_x1[2][(size_t)B_ * 1536];
__device__ __align__(16) __half g_le[(size_t)B_ * 512];
__device__ __align__(16) __half g_h1[2][(size_t)B_ * 512];
#define WI_TOTAL 4718592
__device__ __align__(16) __half g_w[WI_TOTAL];

__constant__ int c_jobK[4]  = {1536, 1536, 512, 1024};
__constant__ int c_wioff[4] = {0, 1572864, 3145728, 3670016};

#define PREP_BLOCKS   (B_ / 2)       // 16384, two rows per block
#define PPK_BASE      PREP_BLOCKS
#define PPK_TOTAL     2304
#define ALL_BLOCKS    (PREP_BLOCKS + PPK_TOTAL)

// ---- PTX helpers (baseline ISA only; no arch-'a' features) ----
__device__ __forceinline__ uint32_t smem_u32(const void* p) {
    uint32_t a;
    asm("{ .reg .u64 t; cvta.to.shared.u64 t, %1; cvt.u32.u64 %0, t; }" : "=r"(a) : "l"(p));
    return a;
}
#define CP_ASYNC16(d, s) asm volatile("cp.async.cg.shared.global [%0], [%1], 16;" :: "r"(d), "l"(s))
#define CP_COMMIT()      asm volatile("cp.async.commit_group;" ::: "memory")
#define CP_WAIT1()       asm volatile("cp.async.wait_group 1;" ::: "memory")
#define CP_WAIT0()       asm volatile("cp.async.wait_group 0;" ::: "memory")
#define LDSM_X4(r, addr) \
    asm volatile("ldmatrix.sync.aligned.m8n8.x4.shared.b16 {%0,%1,%2,%3}, [%4];" \
        : "=r"((r)[0]), "=r"((r)[1]), "=r"((r)[2]), "=r"((r)[3]) : "r"(addr))
#define MMA_F32ACC(c, a, b) \
    asm volatile("mma.sync.aligned.m16n8k16.row.col.f32.f16.f16.f32 " \
        "{%0,%1,%2,%3}, {%4,%5,%6,%7}, {%8,%9}, {%0,%1,%2,%3};" \
        : "+f"((c)[0]), "+f"((c)[1]), "+f"((c)[2]), "+f"((c)[3]) \
        : "r"((a)[0]), "r"((a)[1]), "r"((a)[2]), "r"((a)[3]), "r"((b)[0]), "r"((b)[1]))
#define LD_ACQ(v, p) asm volatile("ld.global.acquire.gpu.b32 %0, [%1];" : "=r"(v) : "l"(p))

// ---- fused prep + weight prepack (one launch; R12-proven) ----
__global__ void __launch_bounds__(NTH)
prep_all_kernel(const float* __restrict__ nh, const float* __restrict__ nc,
                const float* __restrict__ lab, const float* __restrict__ le,
                const int* __restrict__ group,
                float* __restrict__ out_children,
                float* __restrict__ mask_out, int write_mask,
                const float* w0h, const float* w0g, const float* w1h, const float* w1g,
                const float* w2h, const float* w2g, const float* w3h, const float* w3g) {
    int bid = blockIdx.x;
    int tid = threadIdx.x;

    if (bid < PREP_BLOCKS) {
        int half = tid >> 7;
        int tid2 = tid & 127;
        int row  = bid * 2 + half;
        int g = __ldg(group + row);
        __shared__ int s_p[2];
        if (tid2 == 0) {
            if (write_mask) mask_out[row] = (g == 2) ? 1.0f : 0.0f;
            if (g < 2) {
                int p = atomicAdd(&g_cnt[g], 1);
                g_idx[g][p] = row;
                s_p[half] = p;
            }
        }
        __syncthreads();
        if (g == 2) {
            float4 z = make_float4(0.f, 0.f, 0.f, 0.f);
            reinterpret_cast<float4*>(out_children + (size_t)row * H_)[tid2] = z;
            return;
        }
        int p = s_p[half];
        __half* x = g_x1[g];
#pragma unroll
        for (int i = 0; i < 3; ++i) {
            int c4 = tid2 + i * 128;
            const float* srcp = (c4 < 128) ? nh : (c4 < 256) ? nc : lab;
            int loc = (c4 & 127) * 4;
            float4 v = *reinterpret_cast<const float4*>(srcp + (size_t)row * 512 + loc);
            __half h[4];
            h[0] = __float2half_rn(v.x); h[1] = __float2half_rn(v.y);
            h[2] = __float2half_rn(v.z); h[3] = __float2half_rn(v.w);
            *reinterpret_cast<uint2*>(x + (size_t)p * 1536 + c4 * 4) = *reinterpret_cast<uint2*>(h);
        }
        if (g == 1) {
            float4 v = *reinterpret_cast<const float4*>(le + (size_t)row * 512 + tid2 * 4);
            __half h[4];
            h[0] = __float2half_rn(v.x); h[1] = __float2half_rn(v.y);
            h[2] = __float2half_rn(v.z); h[3] = __float2half_rn(v.w);
            *reinterpret_cast<uint2*>(g_le + (size_t)p * 512 + tid2 * 4) = *reinterpret_cast<uint2*>(h);
        }
        return;
    }

    // ---- weight prepack role ----
    int b2 = bid - PPK_BASE;
    int j, base_b;
    if (b2 < 768)       { j = 0; base_b = 0; }
    else if (b2 < 1536) { j = 1; base_b = 768; }
    else if (b2 < 1792) { j = 2; base_b = 1536; }
    else                { j = 3; base_b = 1792; }
    const float* Wh = (j == 0) ? w0h : (j == 1) ? w1h : (j == 2) ? w2h : w3h;
    const float* Wg = (j == 0) ? w0g : (j == 1) ? w1g : (j == 2) ? w2g : w3g;
    int K  = c_jobK[j];
    int nk = K / 32;
    int local = b2 - base_b;
    int k0 = (local % nk) * 32;
    int n0 = (local / nk) * 32;

    __shared__ float sh[32][33], sg[32][33];
    int tx = tid & 31, ty = tid >> 5;
#pragma unroll
    for (int i = 0; i < 4; ++i) {
        sh[ty + 8 * i][tx] = Wh[(size_t)(k0 + ty + 8 * i) * 512 + n0 + tx];
        sg[ty + 8 * i][tx] = Wg[(size_t)(k0 + ty + 8 * i) * 512 + n0 + tx];
    }
    __syncthreads();
    size_t base = (size_t)c_wioff[j];
#pragma unroll
    for (int i = 0; i < 4; ++i) {
        int n = n0 + ty + 8 * i;
        int k = k0 + tx;
        g_w[base + (size_t)(2 * n) * K + k]     = __float2half_rn(sh[tx][ty + 8 * i]);
        g_w[base + (size_t)(2 * n + 1) * K + k] = __float2half_rn(sg[tx][ty + 8 * i]);
    }
}

// ---- stage loader ----
__device__ __forceinline__ void load_stage(uint32_t stu, int job, int br, int m0,
                                           int bx, int k0, int K, int wioff, int tid) {
    const __half* a;
    int astr, acol;
    if (job <= 1)      { a = g_x1[br]; astr = 1536; acol = k0; }
    else if (job == 2) { a = g_h1[0];  astr = 512;  acol = k0; }
    else {
        if (k0 < 512)  { a = g_h1[1];  astr = 512;  acol = k0; }
        else           { a = g_le;     astr = 512;  acol = k0 - 512; }
    }
#pragma unroll
    for (int i = 0; i < 4; ++i) {
        int idx = tid + i * NTH;
        int row = idx >> 3;
        int q   = idx & 7;
        uint32_t d = stu + row * ROWB + q * 16;
        CP_ASYNC16(d, a + (size_t)(m0 + row) * astr + acol + q * 8);
        int grow = bx * 128 + row;
        CP_ASYNC16(d + PLANE_B, g_w + wioff + (size_t)grow * K + k0 + q * 8);
    }
    CP_COMMIT();
}

// ---- ALL four gated GEMMs in ONE launch; y-strided (grid.y=96 covers 256) ----
__global__ void __launch_bounds__(NTH, 2)
gate_gemm_all(const float* __restrict__ bh0, const float* __restrict__ bg0,
              const float* __restrict__ bh1, const float* __restrict__ bg1,
              const float* __restrict__ bh2, const float* __restrict__ bg2,
              const float* __restrict__ bh3, const float* __restrict__ bg3,
              float* __restrict__ out) {
    extern __shared__ char smem[];
    int job = (int)blockIdx.z;
    int br  = (job == 1 || job == 3) ? 1 : 0;
    int mcnt = g_cnt[br];
    int tid = threadIdx.x;
    int bx = blockIdx.x;
    int K  = c_jobK[job];
    int wioff = c_wioff[job];
    uint32_t sb = smem_u32(smem);

    int wid = tid >> 5, lane = tid & 31;
    int wm = (wid & 3) * 32;
    int wn = (wid >> 2) * 64;
    int s0 = wid & 3;                    // fixed stagger (R10/R12-proven)
    uint32_t a_off  = (uint32_t)(wm + (lane & 15)) * ROWB + ((lane >> 4) << 4);
    uint32_t b_rowl = (lane & 7);
    uint32_t b_pair = (lane >> 4);
    uint32_t b_kh   = ((lane >> 3) & 1) * 16;

    for (int by = blockIdx.y; by * CTA_M < mcnt; by += GRID_Y) {
        int m0 = by * CTA_M;

        if (job >= 2) {                  // wait for this row-slice of h1
            if (tid == 0) {
                const int* ctr = &g_rdy[br][by];
                int v;
                while (true) {
                    LD_ACQ(v, ctr);
                    if (v >= 8) break;
                    __nanosleep(128);
                }
            }
            __syncthreads();
        }

        float acc[2][8][4];
#pragma unroll
        for (int i = 0; i < 2; ++i)
#pragma unroll
            for (int j2 = 0; j2 < 8; ++j2)
#pragma unroll
                for (int q = 0; q < 4; ++q) acc[i][j2][q] = 0.f;

        const int nchunks = K / 64;
        load_stage(sb, job, br, m0, bx, 0, K, wioff, tid);

        int slot = 0;
        for (int c = 0; c < nchunks; ++c) {
            int nslot = (slot + 1 == NSTAGE) ? 0 : slot + 1;
            if (c + 1 < nchunks) {
                load_stage(sb + nslot * STAGE_B, job, br, m0, bx, (c + 1) * 64, K, wioff, tid);
                CP_WAIT1();
            } else {
                CP_WAIT0();
            }
            __syncthreads();
            uint32_t stu = sb + slot * STAGE_B;
            slot = nslot;

#pragma unroll
            for (int si = 0; si < 4; ++si) {
                int s = (si + s0) & 3;
                uint32_t koff = (uint32_t)s * 32;
                uint32_t ah[2][4];
#pragma unroll
                for (int tm = 0; tm < 2; ++tm)
                    LDSM_X4(ah[tm], stu + a_off + tm * 16 * ROWB + koff);
                uint32_t bf[8][2];
#pragma unroll
                for (int tn = 0; tn < 8; tn += 2) {
                    uint32_t row = wn + (tn + b_pair) * 8 + b_rowl;
                    uint32_t addr = stu + PLANE_B + row * ROWB + koff + b_kh;
                    uint32_t r[4];
                    LDSM_X4(r, addr);
                    bf[tn][0] = r[0]; bf[tn][1] = r[1];
                    bf[tn + 1][0] = r[2]; bf[tn + 1][1] = r[3];
                }
#pragma unroll
                for (int tm = 0; tm < 2; ++tm)
#pragma unroll
                    for (int tn = 0; tn < 8; ++tn) MMA_F32ACC(acc[tm][tn], ah[tm], bf[tn]);
            }
        }

        // ---- epilogue ----
        const float* bh_p = (job == 0) ? bh0 : (job == 1) ? bh1 : (job == 2) ? bh2 : bh3;
        const float* bg_p = (job == 0) ? bg0 : (job == 1) ? bg1 : (job == 2) ? bg2 : bg3;
        int n_base = bx * 64 + (wid >> 2) * 32 + (lane & 3);
        int m_base = m0 + wm + (lane >> 2);
        __half* h1 = g_h1[br];

#pragma unroll
        for (int tn = 0; tn < 8; ++tn) {
            int n = n_base + tn * 4;
            float bhv = __ldg(bh_p + n);
            float bgv = __ldg(bg_p + n);
#pragma unroll
            for (int tm = 0; tm < 2; ++tm)
#pragma unroll
                for (int rr = 0; rr < 2; ++rr) {
                    int m = m_base + tm * 16 + rr * 8;
                    if (m < mcnt) {
                        float x = acc[tm][tn][rr * 2 + 0] + bhv;
                        float y = acc[tm][tn][rr * 2 + 1] + bgv;
                        float r = tanhf(x) * (1.0f / (1.0f + __expf(-y)));
                        if (job < 2) {
                            h1[(size_t)m * 512 + n] = __float2half_rn(r);
                        } else {
                            out[(size_t)g_idx[br][m] * 512 + n] = r;
                        }
                    }
                }
        }

        if (job < 2) {                   // publish slice completion (release)
            __threadfence();
            __syncthreads();
            if (tid == 0) atomicAdd(&g_rdy[br][by], 1);
        }
        __syncthreads();                 // smem slots free before next by iteration
    }

    // ---- chip-wide completion ticket: last CTA resets state for next replay ----
    __shared__ int s_last;
    __syncthreads();
    if (tid == 0) {
        int total = gridDim.x * gridDim.y * gridDim.z;
        int t = atomicAdd(&g_done, 1);
        s_last = (t == total - 1) ? 1 : 0;
    }
    __syncthreads();
    if (s_last) {                        // parallel reset across 256 threads
        g_rdy[0][tid] = 0;
        g_rdy[1][tid] = 0;
        if (tid < 2) g_cnt[tid] = 0;
        __syncthreads();
        if (tid == 0) { g_done = 0; __threadfence(); }
    }
}

// ---- launch ----
extern "C" void kernel_launch(void* const* d_in, const int* in_sizes, int n_in,
                              void* d_out, int out_size) {
    const float* node_hidden     = (const float*)d_in[0];
    const float* node_context    = (const float*)d_in[1];
    const float* label_embedding = (const float*)d_in[2];
    const float* left_embedding  = (const float*)d_in[3];
    const int*   group           = (const int*)  d_in[4];
    const float* Wl1h = (const float*)d_in[5];
    const float* bl1h = (const float*)d_in[6];
    const float* Wl1g = (const float*)d_in[7];
    const float* bl1g = (const float*)d_in[8];
    const float* Wl2h = (const float*)d_in[9];
    const float* bl2h = (const float*)d_in[10];
    const float* Wl2g = (const float*)d_in[11];
    const float* bl2g = (const float*)d_in[12];
    const float* Wr1h = (const float*)d_in[13];
    const float* br1h = (const float*)d_in[14];
    const float* Wr1g = (const float*)d_in[15];
    const float* br1g = (const float*)d_in[16];
    const float* Wr2h = (const float*)d_in[17];
    const float* br2h = (const float*)d_in[18];
    const float* Wr2g = (const float*)d_in[19];
    const float* br2g = (const float*)d_in[20];
    (void)in_sizes; (void)n_in;

    float* out_children = (float*)d_out;
    float* out_mask     = (float*)d_out + (size_t)B_ * H_;
    int write_mask = (out_size >= (int)((size_t)B_ * H_ + B_)) ? 1 : 0;

    cudaFuncSetAttribute(gate_gemm_all, cudaFuncAttributeMaxDynamicSharedMemorySize, SMEM_DYN);

    prep_all_kernel<<<ALL_BLOCKS, NTH>>>(node_hidden, node_context, label_embedding,
                                         left_embedding, group, out_children,
                                         out_mask, write_mask,
                                         Wl1h, Wl1g, Wr1h, Wr1g,
                                         Wl2h, Wl2g, Wr2h, Wr2g);

    // all 4 GEMM jobs in one launch; y-strided grid (producers precede consumers)
    dim3 grid(H_ / 64, GRID_Y, 4);       // 8 x 96 x 4 = 3072 CTAs
    gate_gemm_all<<<grid, NTH, SMEM_DYN>>>(bl1h, bl1g, br1h, br1g,
                                           bl2h, bl2g, br2h, br2g, out_children);
}